// round 1
// baseline (speedup 1.0000x reference)
#include <cuda_runtime.h>
#include <cuda_fp16.h>
#include <stdint.h>

#define DIM 4096
#define NHEADS 32
#define HD 128
#define BSZ 4
#define SEQ 512
#define MAXSEQ 2048

// ---------------- scratch (device globals; no allocation in kernel_launch) ----------------
static __device__ float g_q[(size_t)BSZ * SEQ * DIM];
static __device__ float g_k[(size_t)BSZ * SEQ * DIM];
static __device__ float g_v[(size_t)BSZ * SEQ * DIM];
static __device__ float g_attn[(size_t)BSZ * SEQ * DIM];
static __device__ float g_sc[(size_t)BSZ * NHEADS * SEQ * SEQ];

// ---------------- mma.sync m16n8k16 f16 x f16 -> f32 ----------------
__device__ __forceinline__ void mma_16816(float* c, const uint32_t* a, const uint32_t* b) {
    asm volatile(
        "mma.sync.aligned.m16n8k16.row.col.f32.f16.f16.f32 "
        "{%0,%1,%2,%3}, {%4,%5,%6,%7}, {%8,%9}, {%0,%1,%2,%3};\n"
        : "+f"(c[0]), "+f"(c[1]), "+f"(c[2]), "+f"(c[3])
        : "r"(a[0]), "r"(a[1]), "r"(a[2]), "r"(a[3]),
          "r"(b[0]), "r"(b[1]));
}

__device__ __forceinline__ uint32_t pack_halves(__half lo, __half hi) {
    __half2 t = __halves2half2(lo, hi);
    return *reinterpret_cast<uint32_t*>(&t);
}

constexpr int BM = 128, BN = 128, BK = 32, PADH = 8;
constexpr float NEGBIG = -1e30f;
constexpr float QK_SCALE = 0.08838834764831845f;  // 1/sqrt(128)

// =====================================================================
// GEMM: C[m][n] = scale[n] * sum_k A[m][k] * W[n][k]
// A fp32 (lda = 4096), W int32 holding int8 values (ld = 4096), C fp32 (ldc = 4096)
// grid: (N/128, M/128), block 256
// =====================================================================
__global__ __launch_bounds__(256) void gemm_w_kernel(
    const float* __restrict__ A, const int* __restrict__ W,
    const float* __restrict__ scale, float* __restrict__ C)
{
    const int K = 4096;
    __shared__ __half As[2][BM][BK + PADH];
    __shared__ __half Bs[2][BN][BK + PADH];

    const int tid  = threadIdx.x;
    const int m0   = blockIdx.y * BM, n0 = blockIdx.x * BN;
    const int warp = tid >> 5, lane = tid & 31;
    const int gid  = lane >> 2, t2 = (lane & 3) * 2;
    const int wm   = (warp & 1) * 64, wn = (warp >> 1) * 32;
    const int lrow = tid >> 3, lcol = (tid & 7) * 4;

    float c[4][4][4];
#pragma unroll
    for (int mt = 0; mt < 4; mt++)
#pragma unroll
        for (int nt = 0; nt < 4; nt++)
#pragma unroll
            for (int r = 0; r < 4; r++) c[mt][nt][r] = 0.f;

    float4 aN[4]; int4 bN[4];
#pragma unroll
    for (int i = 0; i < 4; i++) {
        aN[i] = *(const float4*)(A + (size_t)(m0 + lrow + 32 * i) * K + lcol);
        bN[i] = *(const int4*)(W + (size_t)(n0 + lrow + 32 * i) * K + lcol);
    }
#pragma unroll
    for (int i = 0; i < 4; i++) {
        __half2* pa = (__half2*)&As[0][lrow + 32 * i][lcol];
        pa[0] = __floats2half2_rn(aN[i].x, aN[i].y);
        pa[1] = __floats2half2_rn(aN[i].z, aN[i].w);
        __half2* pb = (__half2*)&Bs[0][lrow + 32 * i][lcol];
        pb[0] = __halves2half2(__int2half_rn(bN[i].x), __int2half_rn(bN[i].y));
        pb[1] = __halves2half2(__int2half_rn(bN[i].z), __int2half_rn(bN[i].w));
    }
    __syncthreads();

    const int nk = K / BK;  // 128
    for (int kt = 0; kt < nk; kt++) {
        const int buf = kt & 1;
        const bool has_next = (kt + 1 < nk);
        if (has_next) {
#pragma unroll
            for (int i = 0; i < 4; i++) {
                aN[i] = *(const float4*)(A + (size_t)(m0 + lrow + 32 * i) * K + (kt + 1) * BK + lcol);
                bN[i] = *(const int4*)(W + (size_t)(n0 + lrow + 32 * i) * K + (kt + 1) * BK + lcol);
            }
        }
#pragma unroll
        for (int kk = 0; kk < BK; kk += 16) {
            uint32_t af[4][4], bf[4][2];
#pragma unroll
            for (int mt = 0; mt < 4; mt++) {
                const int r = wm + mt * 16 + gid;
                af[mt][0] = *(const uint32_t*)&As[buf][r][kk + t2];
                af[mt][1] = *(const uint32_t*)&As[buf][r + 8][kk + t2];
                af[mt][2] = *(const uint32_t*)&As[buf][r][kk + t2 + 8];
                af[mt][3] = *(const uint32_t*)&As[buf][r + 8][kk + t2 + 8];
            }
#pragma unroll
            for (int nt = 0; nt < 4; nt++) {
                const int rn = wn + nt * 8 + gid;
                bf[nt][0] = *(const uint32_t*)&Bs[buf][rn][kk + t2];
                bf[nt][1] = *(const uint32_t*)&Bs[buf][rn][kk + t2 + 8];
            }
#pragma unroll
            for (int mt = 0; mt < 4; mt++)
#pragma unroll
                for (int nt = 0; nt < 4; nt++) mma_16816(c[mt][nt], af[mt], bf[nt]);
        }
        if (has_next) {
#pragma unroll
            for (int i = 0; i < 4; i++) {
                __half2* pa = (__half2*)&As[buf ^ 1][lrow + 32 * i][lcol];
                pa[0] = __floats2half2_rn(aN[i].x, aN[i].y);
                pa[1] = __floats2half2_rn(aN[i].z, aN[i].w);
                __half2* pb = (__half2*)&Bs[buf ^ 1][lrow + 32 * i][lcol];
                pb[0] = __halves2half2(__int2half_rn(bN[i].x), __int2half_rn(bN[i].y));
                pb[1] = __halves2half2(__int2half_rn(bN[i].z), __int2half_rn(bN[i].w));
            }
        }
        __syncthreads();
    }

#pragma unroll
    for (int nt = 0; nt < 4; nt++) {
        const int col = n0 + wn + nt * 8 + t2;
        const float s0 = scale[col], s1 = scale[col + 1];
#pragma unroll
        for (int mt = 0; mt < 4; mt++) {
            const int row = m0 + wm + mt * 16 + gid;
            C[(size_t)row * DIM + col]           = c[mt][nt][0] * s0;
            C[(size_t)row * DIM + col + 1]       = c[mt][nt][1] * s1;
            C[(size_t)(row + 8) * DIM + col]     = c[mt][nt][2] * s0;
            C[(size_t)(row + 8) * DIM + col + 1] = c[mt][nt][3] * s1;
        }
    }
}

// =====================================================================
// RoPE on q,k (in place in scratch) + scatter k,v into cache output.
// grid (BSZ*SEQ, NHEADS), block 64 (one thread per rotary pair)
// =====================================================================
__global__ void rope_cache_kernel(const float* __restrict__ fcos, const float* __restrict__ fsin,
                                  const int* __restrict__ idx,
                                  float* __restrict__ cacheK, float* __restrict__ cacheV)
{
    const int bs = blockIdx.x;       // 0..2047
    const int h  = blockIdx.y;       // 0..31
    const int i  = threadIdx.x;      // 0..63
    const int b  = bs >> 9, s = bs & 511;
    const size_t base = (size_t)bs * DIM + (size_t)h * HD;

    const float cv = fcos[s * 64 + i];
    const float sv = fsin[s * 64 + i];

    const float qr = g_q[base + 2 * i], qi = g_q[base + 2 * i + 1];
    g_q[base + 2 * i]     = qr * cv - qi * sv;
    g_q[base + 2 * i + 1] = qr * sv + qi * cv;

    const float kr = g_k[base + 2 * i], ki = g_k[base + 2 * i + 1];
    const float kor = kr * cv - ki * sv;
    const float koi = kr * sv + ki * cv;
    g_k[base + 2 * i]     = kor;
    g_k[base + 2 * i + 1] = koi;

    const int t = idx[s];
    const size_t cb = ((size_t)(b * MAXSEQ + t) * NHEADS + h) * HD;
    cacheK[cb + 2 * i]     = kor;
    cacheK[cb + 2 * i + 1] = koi;
    cacheV[cb + 2 * i]     = g_v[base + 2 * i];
    cacheV[cb + 2 * i + 1] = g_v[base + 2 * i + 1];
}

// zero cache rows t in [512, 2048)
__global__ void zero_tail_kernel(float4* __restrict__ ck, float4* __restrict__ cv)
{
    const int perB = 1536 * 1024;           // float4 per batch tail
    const int n = BSZ * perB;
    const float4 z = make_float4(0.f, 0.f, 0.f, 0.f);
    for (int i = blockIdx.x * blockDim.x + threadIdx.x; i < n; i += gridDim.x * blockDim.x) {
        const int b = i / perB, r = i - b * perB;
        const size_t off = ((size_t)b * MAXSEQ + SEQ) * (DIM / 4) + r;
        ck[off] = z;
        cv[off] = z;
    }
}

// =====================================================================
// QK^T scores: g_sc[z][q][k] = (q . k)/sqrt(128) with causal mask (k>q -> NEGBIG)
// grid (4, 4, 128), block 256
// =====================================================================
__global__ __launch_bounds__(256) void gemm_qk_kernel()
{
    const int z = blockIdx.z;
    const int b = z >> 5, h = z & 31;
    const int m0 = blockIdx.y * BM, n0 = blockIdx.x * BN;
    float* Cp = g_sc + (size_t)z * SEQ * SEQ;

    if (n0 >= m0 + BM) {  // fully masked tile
        for (int i = threadIdx.x; i < BM * BN; i += 256)
            Cp[(size_t)(m0 + i / BN) * SEQ + n0 + (i % BN)] = NEGBIG;
        return;
    }

    const float* Aq = g_q + (size_t)b * SEQ * DIM + (size_t)h * HD;
    const float* Bk = g_k + (size_t)b * SEQ * DIM + (size_t)h * HD;

    __shared__ __half As[2][BM][BK + PADH];
    __shared__ __half Bs[2][BN][BK + PADH];

    const int tid  = threadIdx.x;
    const int warp = tid >> 5, lane = tid & 31;
    const int gid  = lane >> 2, t2 = (lane & 3) * 2;
    const int wm   = (warp & 1) * 64, wn = (warp >> 1) * 32;
    const int lrow = tid >> 3, lcol = (tid & 7) * 4;

    float c[4][4][4];
#pragma unroll
    for (int mt = 0; mt < 4; mt++)
#pragma unroll
        for (int nt = 0; nt < 4; nt++)
#pragma unroll
            for (int r = 0; r < 4; r++) c[mt][nt][r] = 0.f;

    float4 aN[4], bN[4];
#pragma unroll
    for (int i = 0; i < 4; i++) {
        aN[i] = *(const float4*)(Aq + (size_t)(m0 + lrow + 32 * i) * DIM + lcol);
        bN[i] = *(const float4*)(Bk + (size_t)(n0 + lrow + 32 * i) * DIM + lcol);
    }
#pragma unroll
    for (int i = 0; i < 4; i++) {
        __half2* pa = (__half2*)&As[0][lrow + 32 * i][lcol];
        pa[0] = __floats2half2_rn(aN[i].x, aN[i].y);
        pa[1] = __floats2half2_rn(aN[i].z, aN[i].w);
        __half2* pb = (__half2*)&Bs[0][lrow + 32 * i][lcol];
        pb[0] = __floats2half2_rn(bN[i].x, bN[i].y);
        pb[1] = __floats2half2_rn(bN[i].z, bN[i].w);
    }
    __syncthreads();

    const int nk = HD / BK;  // 4
    for (int kt = 0; kt < nk; kt++) {
        const int buf = kt & 1;
        const bool has_next = (kt + 1 < nk);
        if (has_next) {
#pragma unroll
            for (int i = 0; i < 4; i++) {
                aN[i] = *(const float4*)(Aq + (size_t)(m0 + lrow + 32 * i) * DIM + (kt + 1) * BK + lcol);
                bN[i] = *(const float4*)(Bk + (size_t)(n0 + lrow + 32 * i) * DIM + (kt + 1) * BK + lcol);
            }
        }
#pragma unroll
        for (int kk = 0; kk < BK; kk += 16) {
            uint32_t af[4][4], bf[4][2];
#pragma unroll
            for (int mt = 0; mt < 4; mt++) {
                const int r = wm + mt * 16 + gid;
                af[mt][0] = *(const uint32_t*)&As[buf][r][kk + t2];
                af[mt][1] = *(const uint32_t*)&As[buf][r + 8][kk + t2];
                af[mt][2] = *(const uint32_t*)&As[buf][r][kk + t2 + 8];
                af[mt][3] = *(const uint32_t*)&As[buf][r + 8][kk + t2 + 8];
            }
#pragma unroll
            for (int nt = 0; nt < 4; nt++) {
                const int rn = wn + nt * 8 + gid;
                bf[nt][0] = *(const uint32_t*)&Bs[buf][rn][kk + t2];
                bf[nt][1] = *(const uint32_t*)&Bs[buf][rn][kk + t2 + 8];
            }
#pragma unroll
            for (int mt = 0; mt < 4; mt++)
#pragma unroll
                for (int nt = 0; nt < 4; nt++) mma_16816(c[mt][nt], af[mt], bf[nt]);
        }
        if (has_next) {
#pragma unroll
            for (int i = 0; i < 4; i++) {
                __half2* pa = (__half2*)&As[buf ^ 1][lrow + 32 * i][lcol];
                pa[0] = __floats2half2_rn(aN[i].x, aN[i].y);
                pa[1] = __floats2half2_rn(aN[i].z, aN[i].w);
                __half2* pb = (__half2*)&Bs[buf ^ 1][lrow + 32 * i][lcol];
                pb[0] = __floats2half2_rn(bN[i].x, bN[i].y);
                pb[1] = __floats2half2_rn(bN[i].z, bN[i].w);
            }
        }
        __syncthreads();
    }

#pragma unroll
    for (int mt = 0; mt < 4; mt++)
#pragma unroll
        for (int nt = 0; nt < 4; nt++) {
            const int row = m0 + wm + mt * 16 + gid;
            const int col = n0 + wn + nt * 8 + t2;
            float v0 = c[mt][nt][0] * QK_SCALE; if (col > row)         v0 = NEGBIG;
            float v1 = c[mt][nt][1] * QK_SCALE; if (col + 1 > row)     v1 = NEGBIG;
            float v2 = c[mt][nt][2] * QK_SCALE; if (col > row + 8)     v2 = NEGBIG;
            float v3 = c[mt][nt][3] * QK_SCALE; if (col + 1 > row + 8) v3 = NEGBIG;
            Cp[(size_t)row * SEQ + col]           = v0;
            Cp[(size_t)row * SEQ + col + 1]       = v1;
            Cp[(size_t)(row + 8) * SEQ + col]     = v2;
            Cp[(size_t)(row + 8) * SEQ + col + 1] = v3;
        }
}

// =====================================================================
// Row softmax over g_sc (65536 rows of 512). One warp per row.
// =====================================================================
__global__ __launch_bounds__(256) void softmax_kernel()
{
    const int row  = blockIdx.x * 8 + (threadIdx.x >> 5);
    const int lane = threadIdx.x & 31;
    float* p = g_sc + (size_t)row * SEQ;

    float4 v[4];
    float mx = -3.4e38f;
#pragma unroll
    for (int i = 0; i < 4; i++) {
        v[i] = *(float4*)(p + lane * 4 + i * 128);
        mx = fmaxf(mx, fmaxf(fmaxf(v[i].x, v[i].y), fmaxf(v[i].z, v[i].w)));
    }
#pragma unroll
    for (int o = 16; o > 0; o >>= 1) mx = fmaxf(mx, __shfl_xor_sync(0xffffffffu, mx, o));

    float s = 0.f;
#pragma unroll
    for (int i = 0; i < 4; i++) {
        v[i].x = __expf(v[i].x - mx);
        v[i].y = __expf(v[i].y - mx);
        v[i].z = __expf(v[i].z - mx);
        v[i].w = __expf(v[i].w - mx);
        s += v[i].x + v[i].y + v[i].z + v[i].w;
    }
#pragma unroll
    for (int o = 16; o > 0; o >>= 1) s += __shfl_xor_sync(0xffffffffu, s, o);
    const float r = 1.f / s;
#pragma unroll
    for (int i = 0; i < 4; i++) {
        v[i].x *= r; v[i].y *= r; v[i].z *= r; v[i].w *= r;
        *(float4*)(p + lane * 4 + i * 128) = v[i];
    }
}

// =====================================================================
// PV: g_attn[b*512+q][h*128+d] = sum_j probs[z][q][j] * V[b*512+j][h*128+d]
// grid (1, 4, 128), block 256
// =====================================================================
__global__ __launch_bounds__(256) void gemm_pv_kernel()
{
    const int z = blockIdx.z;
    const int b = z >> 5, h = z & 31;
    const int m0 = blockIdx.y * BM;
    const float* Ap = g_sc + (size_t)z * SEQ * SEQ;
    const float* Vp = g_v + (size_t)b * SEQ * DIM + (size_t)h * HD;

    __shared__ __half As[2][BM][BK + PADH];
    __shared__ __half Bs[2][BK][BN + PADH];

    const int tid  = threadIdx.x;
    const int warp = tid >> 5, lane = tid & 31;
    const int gid  = lane >> 2, t2 = (lane & 3) * 2;
    const int wm   = (warp & 1) * 64, wn = (warp >> 1) * 32;
    const int lrow = tid >> 3, lcol = (tid & 7) * 4;   // for A
    const int krow = tid >> 5, kcol = (tid & 31) * 4;  // for B: 8 rows per pass

    float c[4][4][4];
#pragma unroll
    for (int mt = 0; mt < 4; mt++)
#pragma unroll
        for (int nt = 0; nt < 4; nt++)
#pragma unroll
            for (int r = 0; r < 4; r++) c[mt][nt][r] = 0.f;

    float4 aN[4], bN[4];
#pragma unroll
    for (int i = 0; i < 4; i++) {
        aN[i] = *(const float4*)(Ap + (size_t)(m0 + lrow + 32 * i) * SEQ + lcol);
        bN[i] = *(const float4*)(Vp + (size_t)(krow + 8 * i) * DIM + kcol);
    }
#pragma unroll
    for (int i = 0; i < 4; i++) {
        __half2* pa = (__half2*)&As[0][lrow + 32 * i][lcol];
        pa[0] = __floats2half2_rn(aN[i].x, aN[i].y);
        pa[1] = __floats2half2_rn(aN[i].z, aN[i].w);
        __half2* pb = (__half2*)&Bs[0][krow + 8 * i][kcol];
        pb[0] = __floats2half2_rn(bN[i].x, bN[i].y);
        pb[1] = __floats2half2_rn(bN[i].z, bN[i].w);
    }
    __syncthreads();

    const int nk = SEQ / BK;  // 16
    for (int kt = 0; kt < nk; kt++) {
        const int buf = kt & 1;
        const bool has_next = (kt + 1 < nk);
        if (has_next) {
#pragma unroll
            for (int i = 0; i < 4; i++) {
                aN[i] = *(const float4*)(Ap + (size_t)(m0 + lrow + 32 * i) * SEQ + (kt + 1) * BK + lcol);
                bN[i] = *(const float4*)(Vp + (size_t)((kt + 1) * BK + krow + 8 * i) * DIM + kcol);
            }
        }
#pragma unroll
        for (int kk = 0; kk < BK; kk += 16) {
            uint32_t af[4][4], bf[4][2];
#pragma unroll
            for (int mt = 0; mt < 4; mt++) {
                const int r = wm + mt * 16 + gid;
                af[mt][0] = *(const uint32_t*)&As[buf][r][kk + t2];
                af[mt][1] = *(const uint32_t*)&As[buf][r + 8][kk + t2];
                af[mt][2] = *(const uint32_t*)&As[buf][r][kk + t2 + 8];
                af[mt][3] = *(const uint32_t*)&As[buf][r + 8][kk + t2 + 8];
            }
#pragma unroll
            for (int nt = 0; nt < 4; nt++) {
                const int nn = wn + nt * 8 + gid;
                bf[nt][0] = pack_halves(Bs[buf][kk + t2][nn],     Bs[buf][kk + t2 + 1][nn]);
                bf[nt][1] = pack_halves(Bs[buf][kk + t2 + 8][nn], Bs[buf][kk + t2 + 9][nn]);
            }
#pragma unroll
            for (int mt = 0; mt < 4; mt++)
#pragma unroll
                for (int nt = 0; nt < 4; nt++) mma_16816(c[mt][nt], af[mt], bf[nt]);
        }
        if (has_next) {
#pragma unroll
            for (int i = 0; i < 4; i++) {
                __half2* pa = (__half2*)&As[buf ^ 1][lrow + 32 * i][lcol];
                pa[0] = __floats2half2_rn(aN[i].x, aN[i].y);
                pa[1] = __floats2half2_rn(aN[i].z, aN[i].w);
                __half2* pb = (__half2*)&Bs[buf ^ 1][krow + 8 * i][kcol];
                pb[0] = __floats2half2_rn(bN[i].x, bN[i].y);
                pb[1] = __floats2half2_rn(bN[i].z, bN[i].w);
            }
        }
        __syncthreads();
    }

#pragma unroll
    for (int mt = 0; mt < 4; mt++)
#pragma unroll
        for (int nt = 0; nt < 4; nt++) {
            const int row = m0 + wm + mt * 16 + gid;  // q pos
            const int col = wn + nt * 8 + t2;         // d
            float* d0 = g_attn + (size_t)(b * SEQ + row) * DIM + (size_t)h * HD;
            float* d1 = g_attn + (size_t)(b * SEQ + row + 8) * DIM + (size_t)h * HD;
            d0[col]     = c[mt][nt][0];
            d0[col + 1] = c[mt][nt][1];
            d1[col]     = c[mt][nt][2];
            d1[col + 1] = c[mt][nt][3];
        }
}

// =====================================================================
extern "C" void kernel_launch(void* const* d_in, const int* in_sizes, int n_in,
                              void* d_out, int out_size)
{
    (void)in_sizes; (void)n_in; (void)out_size;
    const float* x    = (const float*)d_in[0];
    const float* fcos = (const float*)d_in[1];
    const float* fsin = (const float*)d_in[2];
    const int*   idx  = (const int*)d_in[4];
    const int*   wq   = (const int*)d_in[7];
    const float* sq   = (const float*)d_in[8];
    const int*   wk   = (const int*)d_in[9];
    const float* sk   = (const float*)d_in[10];
    const int*   wv   = (const int*)d_in[11];
    const float* sv   = (const float*)d_in[12];
    const int*   wo   = (const int*)d_in[13];
    const float* so   = (const float*)d_in[14];

    float* out    = (float*)d_out;
    float* cacheK = out + (size_t)BSZ * SEQ * DIM;                       //  8,388,608
    float* cacheV = cacheK + (size_t)BSZ * MAXSEQ * NHEADS * HD;         // +33,554,432

    float *pq = nullptr, *pk = nullptr, *pv = nullptr, *pa = nullptr;
    cudaGetSymbolAddress((void**)&pq, g_q);
    cudaGetSymbolAddress((void**)&pk, g_k);
    cudaGetSymbolAddress((void**)&pv, g_v);
    cudaGetSymbolAddress((void**)&pa, g_attn);

    dim3 gw(DIM / BN, (BSZ * SEQ) / BM);  // (32, 16)
    gemm_w_kernel<<<gw, 256>>>(x, wq, sq, pq);
    gemm_w_kernel<<<gw, 256>>>(x, wk, sk, pk);
    gemm_w_kernel<<<gw, 256>>>(x, wv, sv, pv);

    rope_cache_kernel<<<dim3(BSZ * SEQ, NHEADS), 64>>>(fcos, fsin, idx, cacheK, cacheV);
    zero_tail_kernel<<<2048, 256>>>((float4*)cacheK, (float4*)cacheV);

    gemm_qk_kernel<<<dim3(SEQ / BN, SEQ / BM, BSZ * NHEADS), 256>>>();
    softmax_kernel<<<(BSZ * NHEADS * SEQ) / 8, 256>>>();
    gemm_pv_kernel<<<dim3(1, SEQ / BM, BSZ * NHEADS), 256>>>();

    gemm_w_kernel<<<gw, 256>>>(pa, wo, so, out);
}